// round 6
// baseline (speedup 1.0000x reference)
#include <cuda_runtime.h>
#include <math.h>

#define TT 512
#define BB 32
#define II 512
#define HH 1024
#define BH (BB*HH)
#define TBH (TT*BB*HH)
#define NBLK 128

__device__ float g_P[(size_t)4 * TBH];
__device__ float g_h[BH];
__device__ float g_c[2][BH];
__device__ float g_po[BH];
__device__ float g_acc[6 * 1024 * 32];
__device__ float g_bias[4][HH];
__device__ float g_Wpk[(size_t)7 * 64 * 16384];   // recurrent weights, frag-packed
__device__ float g_WpkI[(size_t)4 * 64 * 8192];   // input weights, frag-packed
__device__ __align__(16) unsigned g_fA[128];
__device__ __align__(16) unsigned g_fB[128];
__device__ __align__(16) unsigned g_fC[64];

__device__ __forceinline__ unsigned cvt_tf32(float x) {
    unsigned r; asm("cvt.rna.tf32.f32 %0, %1;" : "=r"(r) : "f"(x)); return r;
}
__device__ __forceinline__ void st4tf(float* p, float4 v) {
    uint4 u; u.x = cvt_tf32(v.x); u.y = cvt_tf32(v.y);
    u.z = cvt_tf32(v.z); u.w = cvt_tf32(v.w); *(uint4*)p = u;
}
__device__ __forceinline__ void mma_tf32(float* d, uint4 a, unsigned b0, unsigned b1) {
    asm("mma.sync.aligned.m16n8k8.row.col.f32.tf32.tf32.f32 "
        "{%0,%1,%2,%3},{%4,%5,%6,%7},{%8,%9},{%0,%1,%2,%3};"
        : "+f"(d[0]), "+f"(d[1]), "+f"(d[2]), "+f"(d[3])
        : "r"(a.x), "r"(a.y), "r"(a.z), "r"(a.w), "r"(b0), "r"(b1));
}

// flag barrier: signal own flag, then wait until n flags >= v (warp 0 polls)
__device__ __forceinline__ void bar_signal(unsigned* f, int bId, unsigned v) {
    __syncthreads();
    if (threadIdx.x == 0) {
        __threadfence();
        asm volatile("st.relaxed.gpu.global.u32 [%0], %1;"
                     :: "l"(f + bId), "r"(v) : "memory");
    }
}
__device__ __forceinline__ void bar_wait(const unsigned* f, int n, unsigned v) {
    if (threadIdx.x < 32) {
        int i = threadIdx.x * 4;
        const unsigned* p = f + i;
        bool active = i < n;
        for (;;) {
            unsigned x0 = v, x1 = v, x2 = v, x3 = v;
            if (active)
                asm volatile("ld.relaxed.gpu.global.v4.u32 {%0,%1,%2,%3},[%4];"
                             : "=r"(x0), "=r"(x1), "=r"(x2), "=r"(x3) : "l"(p));
            bool ok = (x0 >= v) && (x1 >= v) && (x2 >= v) && (x3 >= v);
            if (__all_sync(0xffffffffu, ok)) break;
        }
        __threadfence();
    }
    __syncthreads();
}

__global__ void __launch_bounds__(256) init_kernel(
    const float* __restrict__ h0, const float* __restrict__ c0,
    const float* __restrict__ b_ii, const float* __restrict__ b_hi,
    const float* __restrict__ b_ci, const float* __restrict__ b_if,
    const float* __restrict__ b_hf, const float* __restrict__ b_cf,
    const float* __restrict__ b_ic, const float* __restrict__ b_hc,
    const float* __restrict__ b_io, const float* __restrict__ b_ho,
    const float* __restrict__ b_cyo)
{
    int i = blockIdx.x * blockDim.x + threadIdx.x;
    if (i < BH) { g_h[i] = h0[i]; g_c[0][i] = c0[i]; }
    if (i < HH) {
        g_bias[0][i] = b_ii[i] + b_hi[i] + b_ci[i];
        g_bias[1][i] = b_if[i] + b_hf[i] + b_cf[i];
        g_bias[2][i] = b_ic[i] + b_hc[i];
        g_bias[3][i] = b_io[i] + b_ho[i] + b_cyo[i];
    }
    if (i < 128) { g_fA[i] = 0; g_fB[i] = 0; }
    if (i < 64)  { g_fC[i] = 0; }
}

// pack 7 recurrent HxH matrices: [tile=mat*64+ng][kt 0..127][lane][jj]
__global__ void __launch_bounds__(256) pack_kernel(
    const float* __restrict__ w0, const float* __restrict__ w1,
    const float* __restrict__ w2, const float* __restrict__ w3,
    const float* __restrict__ w4, const float* __restrict__ w5,
    const float* __restrict__ w6)
{
    int gid = blockIdx.x * 256 + threadIdx.x;
    int mat = gid >> 20, rem = gid & 1048575;
    int ng = rem >> 14, kt = (rem >> 7) & 127, lane = (rem >> 2) & 31, jj = rem & 3;
    int row = ng * 16 + (lane >> 2) + 8 * (jj & 1);
    int col = kt * 8 + (lane & 3) + 4 * (jj >> 1);
    const float* W = (mat == 0) ? w0 : (mat == 1) ? w1 : (mat == 2) ? w2 :
                     (mat == 3) ? w3 : (mat == 4) ? w4 : (mat == 5) ? w5 : w6;
    g_Wpk[gid] = __uint_as_float(cvt_tf32(__ldg(&W[row * HH + col])));
}

// pack 4 input HxI matrices
__global__ void __launch_bounds__(256) pack_in_kernel(
    const float* __restrict__ w0, const float* __restrict__ w1,
    const float* __restrict__ w2, const float* __restrict__ w3)
{
    int gid = blockIdx.x * 256 + threadIdx.x;
    int mat = gid >> 19, rem = gid & 524287;
    int ng = rem >> 13, kt = (rem >> 7) & 63, lane = (rem >> 2) & 31, jj = rem & 3;
    int row = ng * 16 + (lane >> 2) + 8 * (jj & 1);
    int col = kt * 8 + (lane & 3) + 4 * (jj >> 1);
    const float* W = (mat == 0) ? w0 : (mat == 1) ? w1 : (mat == 2) ? w2 : w3;
    g_WpkI[gid] = __uint_as_float(cvt_tf32(__ldg(&W[row * II + col])));
}

// proj (tf32 mma): P[g][m][n] = X @ Wg^T + bias
#define PROJ_SMEM (32768 + 2*2176 + 2176 + 64)
__global__ void __launch_bounds__(256) proj2_kernel(const float* __restrict__ X)
{
    extern __shared__ float smem[];
    float* sA = smem;
    float* sX = smem + 32768;
    float* sT = smem + 32768 + 4352;
    float* sBias = sT + 2176;

    const int tid = threadIdx.x;
    const int bn = blockIdx.x & 63, bm = blockIdx.x >> 6;
    const int w = tid >> 5, lane = tid & 31;
    const int ta = w >> 1, mh = w & 1;

    {
        const float4* src = (const float4*)(g_WpkI + (size_t)(bn * 4) * 8192);
        float4* dst = (float4*)sA;
        for (int p = tid; p < 8192; p += 256) dst[p] = __ldg(src + p);
    }
    if (tid < 64) {
        int np = bn * 64 + tid;
        sBias[tid] = g_bias[np >> 10][np & 1023];
    }

    const int v1 = tid + 256;
    const int b0s = tid >> 4, kq0 = (tid & 15) * 4;
    const int b1s = v1 >> 4,  kq1 = (v1 & 15) * 4;
    const int brow0 = (mh * 16 + (lane >> 2)) * 68 + (lane & 3);
    const int brow1 = (mh * 16 + 8 + (lane >> 2)) * 68 + (lane & 3);

    const float* tilebase = sA + ta * 8192;
    const int gate = (bn * 64) >> 10;
    const int nbase = (bn * 64) & 1023;
    __syncthreads();

    for (int mc = 0; mc < 256; mc++) {
        const int m0 = bm * 8192 + mc * 32;

        float acc[2][4];
#pragma unroll
        for (int g = 0; g < 2; g++)
#pragma unroll
            for (int j = 0; j < 4; j++) acc[g][j] = 0.f;

        float4 px0 = __ldg((const float4*)(X + (size_t)(m0 + b0s) * II + kq0));
        float4 px1 = __ldg((const float4*)(X + (size_t)(m0 + b1s) * II + kq1));

        for (int j = 0; j < 8; j++) {
            float* xb = sX + (j & 1) * 2176;
            __syncthreads();
            st4tf(xb + b0s * 68 + kq0, px0);
            st4tf(xb + b1s * 68 + kq1, px1);
            __syncthreads();
            if (j < 7) {
                int k1 = (j + 1) * 64;
                px0 = __ldg((const float4*)(X + (size_t)(m0 + b0s) * II + k1 + kq0));
                px1 = __ldg((const float4*)(X + (size_t)(m0 + b1s) * II + k1 + kq1));
            }
#pragma unroll
            for (int kt = 0; kt < 8; kt++) {
                const int colo = kt * 8;
                unsigned x0a = *(const unsigned*)(xb + brow0 + colo);
                unsigned x1a = *(const unsigned*)(xb + brow0 + colo + 4);
                unsigned x0b = *(const unsigned*)(xb + brow1 + colo);
                unsigned x1b = *(const unsigned*)(xb + brow1 + colo + 4);
                uint4 a = *(const uint4*)(tilebase + (j * 8 + kt) * 128 + lane * 4);
                mma_tf32(acc[0], a, x0a, x1a);
                mma_tf32(acc[1], a, x0b, x1b);
            }
        }

        __syncthreads();
#pragma unroll
        for (int g = 0; g < 2; g++)
#pragma unroll
            for (int j = 0; j < 4; j++) {
                int nrow = ta * 16 + (lane >> 2) + 8 * (j >> 1);
                int mcol = mh * 16 + g * 8 + 2 * (lane & 3) + (j & 1);
                sT[mcol * 68 + nrow] = acc[g][j];
            }
        __syncthreads();
#pragma unroll
        for (int e = 0; e < 2; e++) {
            int idx = tid + e * 256;
            int row = idx >> 4, q = idx & 15;
            float4 v = *(float4*)(sT + row * 68 + q * 4);
            v.x += sBias[q * 4 + 0]; v.y += sBias[q * 4 + 1];
            v.z += sBias[q * 4 + 2]; v.w += sBias[q * 4 + 3];
            *(float4*)(g_P + (size_t)gate * TBH + (size_t)(m0 + row) * HH + nbase + q * 4) = v;
        }
    }
}

// persistent tf32 recurrence
#define SMEM_FLOATS (49152 + 8704)
extern "C" __global__ void __launch_bounds__(256) lstm_kernel(float* __restrict__ out)
{
    extern __shared__ float smem[];
    float* sW  = smem;
    float* sB  = smem + 49152;
    float* sBh = sB;
    float* sBc = sB + 2 * 2176;

    const int tid = threadIdx.x, bId = blockIdx.x;
    const int w = tid >> 5, lane = tid & 31;
    const int kw = w >> 1, bgset = w & 1;

    const int s0 = 3 * bId;
    const int mats0 = s0 >> 6, mats1 = (s0 + 1) >> 6, mats2 = (s0 + 2) >> 6;
    const bool uC0 = mats0 >= 4, uC1 = mats1 >= 4, uC2 = mats2 >= 4;
    const bool needH = !(uC0 && uC1 && uC2);   // blocks 0..85
    const bool needC = uC0 || uC1 || uC2;

#pragma unroll
    for (int tt = 0; tt < 3; tt++) {
        const float4* src = (const float4*)(g_Wpk + (size_t)(s0 + tt) * 16384);
        float4* dst = (float4*)(sW + tt * 16384);
        for (int p = tid; p < 4096; p += 256) dst[p] = __ldg(src + p);
    }

    const int v1 = tid + 256;
    const int b0s = tid >> 4, kq0 = (tid & 15) * 4;
    const int b1s = v1 >> 4,  kq1 = (v1 & 15) * 4;
    const int brow0 = (bgset * 16 + (lane >> 2)) * 68 + (lane & 3);
    const int brow1 = (bgset * 16 + 8 + (lane >> 2)) * 68 + (lane & 3);

    __syncthreads();

    for (int t = 0; t < TT; t++) {
        const int cur = t & 1, nxt = cur ^ 1;
        const float* c_in = g_c[cur];

        // ---------- phase 1 ----------
        float acc[3][2][4];
#pragma unroll
        for (int a = 0; a < 3; a++)
#pragma unroll
            for (int g = 0; g < 2; g++)
#pragma unroll
                for (int j = 0; j < 4; j++) acc[a][g][j] = 0.f;

        auto p1body = [&](int J, float4& PH0, float4& PH1, float4& PC0, float4& PC1) {
            float* bh = sBh + (J & 1) * 2176;
            float* bc = sBc + (J & 1) * 2176;
            __syncthreads();
            if (needH) { st4tf(bh + b0s * 68 + kq0, PH0); st4tf(bh + b1s * 68 + kq1, PH1); }
            if (needC) { st4tf(bc + b0s * 68 + kq0, PC0); st4tf(bc + b1s * 68 + kq1, PC1); }
            __syncthreads();
            if (J < 14) {
                int k2 = (J + 2) * 64;
                if (needH) {
                    PH0 = __ldcg((const float4*)(g_h + b0s * HH + k2 + kq0));
                    PH1 = __ldcg((const float4*)(g_h + b1s * HH + k2 + kq1));
                }
                if (needC) {
                    PC0 = __ldcg((const float4*)(c_in + b0s * HH + k2 + kq0));
                    PC1 = __ldcg((const float4*)(c_in + b1s * HH + k2 + kq1));
                }
            }
#pragma unroll
            for (int q = 0; q < 2; q++) {
                const int kt = kw * 2 + q, colo = kt * 8;
                unsigned h0a = 0, h1a = 0, h0b = 0, h1b = 0;
                unsigned c0a = 0, c1a = 0, c0b = 0, c1b = 0;
                if (needH) {
                    h0a = *(const unsigned*)(bh + brow0 + colo);
                    h1a = *(const unsigned*)(bh + brow0 + colo + 4);
                    h0b = *(const unsigned*)(bh + brow1 + colo);
                    h1b = *(const unsigned*)(bh + brow1 + colo + 4);
                }
                if (needC) {
                    c0a = *(const unsigned*)(bc + brow0 + colo);
                    c1a = *(const unsigned*)(bc + brow0 + colo + 4);
                    c0b = *(const unsigned*)(bc + brow1 + colo);
                    c1b = *(const unsigned*)(bc + brow1 + colo + 4);
                }
                const int gkt = J * 8 + kt;
                uint4 a0 = *(const uint4*)(sW + gkt * 128 + lane * 4);
                uint4 a1 = *(const uint4*)(sW + 16384 + gkt * 128 + lane * 4);
                uint4 a2 = *(const uint4*)(sW + 32768 + gkt * 128 + lane * 4);
                mma_tf32(acc[0][0], a0, uC0 ? c0a : h0a, uC0 ? c1a : h1a);
                mma_tf32(acc[0][1], a0, uC0 ? c0b : h0b, uC0 ? c1b : h1b);
                mma_tf32(acc[1][0], a1, uC1 ? c0a : h0a, uC1 ? c1a : h1a);
                mma_tf32(acc[1][1], a1, uC1 ? c0b : h0b, uC1 ? c1b : h1b);
                mma_tf32(acc[2][0], a2, uC2 ? c0a : h0a, uC2 ? c1a : h1a);
                mma_tf32(acc[2][1], a2, uC2 ? c0b : h0b, uC2 ? c1b : h1b);
            }
        };

        float4 hA0, hA1, cA0, cA1, hB0, hB1, cB0, cB1;
        if (needH) {
            hA0 = __ldcg((const float4*)(g_h + b0s * HH + kq0));
            hA1 = __ldcg((const float4*)(g_h + b1s * HH + kq1));
            hB0 = __ldcg((const float4*)(g_h + b0s * HH + 64 + kq0));
            hB1 = __ldcg((const float4*)(g_h + b1s * HH + 64 + kq1));
        }
        if (needC) {
            cA0 = __ldcg((const float4*)(c_in + b0s * HH + kq0));
            cA1 = __ldcg((const float4*)(c_in + b1s * HH + kq1));
            cB0 = __ldcg((const float4*)(c_in + b0s * HH + 64 + kq0));
            cB1 = __ldcg((const float4*)(c_in + b1s * HH + 64 + kq1));
        }
        for (int jj = 0; jj < 8; jj++) {
            p1body(2 * jj,     hA0, hA1, cA0, cA1);
            p1body(2 * jj + 1, hB0, hB1, cB0, cB1);
        }

        __syncthreads();
        if (kw > 0) {
            float* dst = sB + (((kw - 1) * 2 + bgset) * 32 + lane) * 24;
#pragma unroll
            for (int a = 0; a < 3; a++)
#pragma unroll
                for (int g = 0; g < 2; g++)
#pragma unroll
                    for (int j = 0; j < 4; j++) dst[a * 8 + g * 4 + j] = acc[a][g][j];
        }
        __syncthreads();
        if (kw == 0) {
#pragma unroll
            for (int r = 0; r < 3; r++) {
                const float* sp = sB + ((r * 2 + bgset) * 32 + lane) * 24;
#pragma unroll
                for (int a = 0; a < 3; a++)
#pragma unroll
                    for (int g = 0; g < 2; g++)
#pragma unroll
                        for (int j = 0; j < 4; j++) acc[a][g][j] += sp[a * 8 + g * 4 + j];
            }
#pragma unroll
            for (int a = 0; a < 3; a++) {
                const int mat = (s0 + a) >> 6, ng = (s0 + a) & 63;
#pragma unroll
                for (int g = 0; g < 2; g++)
#pragma unroll
                    for (int j = 0; j < 4; j++) {
                        int row = ng * 16 + (lane >> 2) + 8 * (j >> 1);
                        int bcol = bgset * 16 + g * 8 + 2 * (lane & 3) + (j & 1);
                        g_acc[((mat << 10) + row) * 32 + bcol] = acc[a][g][j];
                    }
            }
        }
        bar_signal(g_fA, bId, (unsigned)(t + 1));
        bar_wait(g_fA, 128, (unsigned)(t + 1));

        // ---------- pointwise ----------
        {
            int idx = bId * 256 + tid;
            int n = idx >> 5, b = idx & 31;
            int off = b * HH + n;
            size_t pb = (size_t)t * BH + off;
            float hi = __ldcg(&g_acc[n * 32 + b]);
            float hf = __ldcg(&g_acc[(1024 + n) * 32 + b]);
            float hc = __ldcg(&g_acc[(2048 + n) * 32 + b]);
            float ho = __ldcg(&g_acc[(3072 + n) * 32 + b]);
            float ci = __ldcg(&g_acc[(4096 + n) * 32 + b]);
            float cf = __ldcg(&g_acc[(5120 + n) * 32 + b]);
            float cold = __ldcg(&g_c[cur][off]);
            float pi = __ldg(&g_P[pb]) + hi + ci;
            float pf = __ldg(&g_P[(size_t)TBH + pb]) + hf + cf;
            float pg = __ldg(&g_P[2 * (size_t)TBH + pb]) + hc;
            float po = __ldg(&g_P[3 * (size_t)TBH + pb]) + ho;
            float iv = 1.f / (1.f + expf(-pi));
            float fv = 1.f / (1.f + expf(-pf));
            float gv = tanhf(pg);
            float cy = fmaf(fv, cold, iv * gv);
            g_c[nxt][off] = cy;
            g_po[off] = po;
        }
        bar_signal(g_fB, bId, (unsigned)(t + 1));
        bar_wait(g_fB, 128, (unsigned)(t + 1));

        // ---------- phase 2 (blocks 0..63) ----------
        if (bId < 64) {
            float acc2[2][4];
#pragma unroll
            for (int g = 0; g < 2; g++)
#pragma unroll
                for (int j = 0; j < 4; j++) acc2[g][j] = 0.f;

            float* sCy = sBh;
            float* sA2 = sBc;
            const float* cyp = g_c[nxt];
            const float* wsrc = g_Wpk + (size_t)(384 + bId) * 16384;

            auto p2body = [&](int J, float4& PY0, float4& PY1, float4& PA) {
                float* cb = sCy + (J & 1) * 2176;
                float* ab = sA2 + (J & 1) * 1088;
                __syncthreads();
                st4tf(cb + b0s * 68 + kq0, PY0);
                st4tf(cb + b1s * 68 + kq1, PY1);
                *(float4*)(ab + tid * 4) = PA;
                __syncthreads();
                if (J < 14) {
                    int k2 = (J + 2) * 64;
                    PY0 = __ldcg((const float4*)(cyp + b0s * HH + k2 + kq0));
                    PY1 = __ldcg((const float4*)(cyp + b1s * HH + k2 + kq1));
                    PA  = __ldg((const float4*)(wsrc + (J + 2) * 1024) + tid);
                }
#pragma unroll
                for (int q = 0; q < 2; q++) {
                    const int kt = kw * 2 + q, colo = kt * 8;
                    unsigned y0a = *(const unsigned*)(cb + brow0 + colo);
                    unsigned y1a = *(const unsigned*)(cb + brow0 + colo + 4);
                    unsigned y0b = *(const unsigned*)(cb + brow1 + colo);
                    unsigned y1b = *(const unsigned*)(cb + brow1 + colo + 4);
                    uint4 af = *(const uint4*)(ab + kt * 128 + lane * 4);
                    mma_tf32(acc2[0], af, y0a, y1a);
                    mma_tf32(acc2[1], af, y0b, y1b);
                }
            };

            float4 yA0 = __ldcg((const float4*)(cyp + b0s * HH + kq0));
            float4 yA1 = __ldcg((const float4*)(cyp + b1s * HH + kq1));
            float4 aA  = __ldg((const float4*)(wsrc) + tid);
            float4 yB0 = __ldcg((const float4*)(cyp + b0s * HH + 64 + kq0));
            float4 yB1 = __ldcg((const float4*)(cyp + b1s * HH + 64 + kq1));
            float4 aB  = __ldg((const float4*)(wsrc + 1024) + tid);

            for (int jj = 0; jj < 8; jj++) {
                p2body(2 * jj,     yA0, yA1, aA);
                p2body(2 * jj + 1, yB0, yB1, aB);
            }

            __syncthreads();
            if (kw > 0) {
                float* dst = sCy + (((kw - 1) * 2 + bgset) * 32 + lane) * 8;
#pragma unroll
                for (int g = 0; g < 2; g++)
#pragma unroll
                    for (int j = 0; j < 4; j++) dst[g * 4 + j] = acc2[g][j];
            }
            __syncthreads();
            if (kw == 0) {
#pragma unroll
                for (int r = 0; r < 3; r++) {
                    const float* sp = sCy + ((r * 2 + bgset) * 32 + lane) * 8;
#pragma unroll
                    for (int g = 0; g < 2; g++)
#pragma unroll
                        for (int j = 0; j < 4; j++) acc2[g][j] += sp[g * 4 + j];
                }
#pragma unroll
                for (int g = 0; g < 2; g++)
#pragma unroll
                    for (int j = 0; j < 4; j++) {
                        int row = bId * 16 + (lane >> 2) + 8 * (j >> 1);
                        int bcol = bgset * 16 + g * 8 + 2 * (lane & 3) + (j & 1);
                        int off = bcol * HH + row;
                        float po = __ldcg(&g_po[off]);
                        float cyv = __ldcg(&g_c[nxt][off]);
                        float o = 1.f / (1.f + expf(-(po + acc2[g][j])));
                        float hy = o * tanhf(cyv);
                        g_h[off] = hy;
                        out[(size_t)t * BH + off] = hy;
                    }
            }
            bar_signal(g_fC, bId, (unsigned)(t + 1));
        }
        if (needH) bar_wait(g_fC, 64, (unsigned)(t + 1));
    }
}

extern "C" void kernel_launch(void* const* d_in, const int* in_sizes, int n_in,
                              void* d_out, int out_size)
{
    const float* X     = (const float*)d_in[0];
    const float* h0    = (const float*)d_in[1];
    const float* c0    = (const float*)d_in[2];
    const float* w_ii  = (const float*)d_in[3];
    const float* w_hi  = (const float*)d_in[4];
    const float* w_ci  = (const float*)d_in[5];
    const float* w_if  = (const float*)d_in[6];
    const float* w_hf  = (const float*)d_in[7];
    const float* w_cf  = (const float*)d_in[8];
    const float* w_ic  = (const float*)d_in[9];
    const float* w_hc  = (const float*)d_in[10];
    const float* w_io  = (const float*)d_in[11];
    const float* w_ho  = (const float*)d_in[12];
    const float* w_cyo = (const float*)d_in[13];
    float* out = (float*)d_out;

    cudaFuncSetAttribute(lstm_kernel,
                         cudaFuncAttributeMaxDynamicSharedMemorySize,
                         SMEM_FLOATS * 4);
    cudaFuncSetAttribute(proj2_kernel,
                         cudaFuncAttributeMaxDynamicSharedMemorySize,
                         PROJ_SMEM * 4);

    init_kernel<<<128, 256>>>(h0, c0,
        (const float*)d_in[14], (const float*)d_in[15], (const float*)d_in[16],
        (const float*)d_in[17], (const float*)d_in[18], (const float*)d_in[19],
        (const float*)d_in[20], (const float*)d_in[21], (const float*)d_in[22],
        (const float*)d_in[23], (const float*)d_in[24]);
    pack_kernel<<<28672, 256>>>(w_hi, w_hf, w_hc, w_ho, w_ci, w_cf, w_cyo);
    pack_in_kernel<<<8192, 256>>>(w_ii, w_if, w_ic, w_io);
    proj2_kernel<<<128, 256, PROJ_SMEM * 4>>>(X);
    lstm_kernel<<<NBLK, 256, SMEM_FLOATS * 4>>>(out);
}

// round 7
// speedup vs baseline: 1.4512x; 1.4512x over previous
#include <cuda_runtime.h>
#include <math.h>

#define TT 512
#define BB 32
#define II 512
#define HH 1024
#define BH (BB*HH)
#define TBH (TT*BB*HH)
#define NBLK 128

__device__ float g_P[(size_t)4 * TBH];
__device__ float g_h[BH];
__device__ float g_c[2][BH];
__device__ float g_po[BH];
__device__ float g_bias[4][HH];
__device__ float g_Wpk[(size_t)448 * 16384];      // 384 phase1 tiles + 64 Wcyo tiles
__device__ float g_WpkI[(size_t)4 * 64 * 8192];   // input weights, frag-packed
__device__ unsigned g_cntB;
__device__ volatile unsigned g_genB;
__device__ unsigned g_cntC;
__device__ volatile unsigned g_genC;

__device__ __forceinline__ unsigned cvt_tf32(float x) {
    unsigned r; asm("cvt.rna.tf32.f32 %0, %1;" : "=r"(r) : "f"(x)); return r;
}
__device__ __forceinline__ void st4tf(float* p, float4 v) {
    uint4 u; u.x = cvt_tf32(v.x); u.y = cvt_tf32(v.y);
    u.z = cvt_tf32(v.z); u.w = cvt_tf32(v.w); *(uint4*)p = u;
}
__device__ __forceinline__ void mma_tf32(float* d, uint4 a, unsigned b0, unsigned b1) {
    asm("mma.sync.aligned.m16n8k8.row.col.f32.tf32.tf32.f32 "
        "{%0,%1,%2,%3},{%4,%5,%6,%7},{%8,%9},{%0,%1,%2,%3};"
        : "+f"(d[0]), "+f"(d[1]), "+f"(d[2]), "+f"(d[3])
        : "r"(a.x), "r"(a.y), "r"(a.z), "r"(a.w), "r"(b0), "r"(b1));
}

// R4-style atomic barrier: 1 polling thread per block, monotonic generation.
__device__ __forceinline__ void gbar(unsigned* cnt, volatile unsigned* gen,
                                     int nArr, unsigned target,
                                     bool arrive, bool wait) {
    __syncthreads();
    if (threadIdx.x == 0) {
        if (arrive) {
            __threadfence();
            unsigned old = atomicAdd(cnt, 1);
            if (old == (unsigned)(nArr - 1)) {
                atomicExch(cnt, 0);
                __threadfence();
                *gen = target;
            }
        }
        if (wait) {
            while (*gen < target) { }
            __threadfence();
        }
    }
    __syncthreads();
}

__global__ void __launch_bounds__(256) init_kernel(
    const float* __restrict__ h0, const float* __restrict__ c0,
    const float* __restrict__ b_ii, const float* __restrict__ b_hi,
    const float* __restrict__ b_ci, const float* __restrict__ b_if,
    const float* __restrict__ b_hf, const float* __restrict__ b_cf,
    const float* __restrict__ b_ic, const float* __restrict__ b_hc,
    const float* __restrict__ b_io, const float* __restrict__ b_ho,
    const float* __restrict__ b_cyo)
{
    int i = blockIdx.x * blockDim.x + threadIdx.x;
    if (i < BH) { g_h[i] = h0[i]; g_c[0][i] = c0[i]; }
    if (i < HH) {
        g_bias[0][i] = b_ii[i] + b_hi[i] + b_ci[i];
        g_bias[1][i] = b_if[i] + b_hf[i] + b_cf[i];
        g_bias[2][i] = b_ic[i] + b_hc[i];
        g_bias[3][i] = b_io[i] + b_ho[i] + b_cyo[i];
    }
    if (i == 0) { g_cntB = 0; g_genB = 0; g_cntC = 0; g_genC = 0; }
}

// Pack weights into m16n8k8 A-fragment order.
// Tiles 0..383: phase-1. Tile s = 3*bId + tt. Within tile, A-frag row
// r = (lane>>2) + 8*(jj&1); mat = tt*2 + (r>>3); n = bId*8 + (r&7).
// Tiles 384..447: Wcyo, row = ng*16 + (lane>>2) + 8*(jj&1).
__global__ void __launch_bounds__(256) pack_kernel(
    const float* __restrict__ w0, const float* __restrict__ w1,
    const float* __restrict__ w2, const float* __restrict__ w3,
    const float* __restrict__ w4, const float* __restrict__ w5,
    const float* __restrict__ w6)
{
    int gid = blockIdx.x * 256 + threadIdx.x;
    int s = gid >> 14, rem = gid & 16383;
    int kt = rem >> 7, lane = (rem >> 2) & 31, jj = rem & 3;
    int kcol = kt * 8 + (lane & 3) + 4 * (jj >> 1);
    float v;
    if (s < 384) {
        int bId = s / 3, tt = s - 3 * bId;
        int r = (lane >> 2) + 8 * (jj & 1);
        int mat = tt * 2 + (r >> 3);
        int n = bId * 8 + (r & 7);
        const float* W = (mat == 0) ? w0 : (mat == 1) ? w1 : (mat == 2) ? w2 :
                         (mat == 3) ? w3 : (mat == 4) ? w4 : w5;
        v = __ldg(&W[n * HH + kcol]);
    } else {
        int ng = s - 384;
        int row = ng * 16 + (lane >> 2) + 8 * (jj & 1);
        v = __ldg(&w6[row * HH + kcol]);
    }
    g_Wpk[gid] = __uint_as_float(cvt_tf32(v));
}

__global__ void __launch_bounds__(256) pack_in_kernel(
    const float* __restrict__ w0, const float* __restrict__ w1,
    const float* __restrict__ w2, const float* __restrict__ w3)
{
    int gid = blockIdx.x * 256 + threadIdx.x;
    int mat = gid >> 19, rem = gid & 524287;
    int ng = rem >> 13, kt = (rem >> 7) & 63, lane = (rem >> 2) & 31, jj = rem & 3;
    int row = ng * 16 + (lane >> 2) + 8 * (jj & 1);
    int col = kt * 8 + (lane & 3) + 4 * (jj >> 1);
    const float* W = (mat == 0) ? w0 : (mat == 1) ? w1 : (mat == 2) ? w2 : w3;
    g_WpkI[gid] = __uint_as_float(cvt_tf32(__ldg(&W[row * II + col])));
}

// proj (tf32 mma): P[g][m][n] = X @ Wg^T + bias
#define PROJ_SMEM (32768 + 2*2176 + 2176 + 64)
__global__ void __launch_bounds__(256) proj2_kernel(const float* __restrict__ X)
{
    extern __shared__ float smem[];
    float* sA = smem;
    float* sX = smem + 32768;
    float* sT = smem + 32768 + 4352;
    float* sBias = sT + 2176;

    const int tid = threadIdx.x;
    const int bn = blockIdx.x & 63, bm = blockIdx.x >> 6;
    const int w = tid >> 5, lane = tid & 31;
    const int ta = w >> 1, mh = w & 1;

    {
        const float4* src = (const float4*)(g_WpkI + (size_t)(bn * 4) * 8192);
        float4* dst = (float4*)sA;
        for (int p = tid; p < 8192; p += 256) dst[p] = __ldg(src + p);
    }
    if (tid < 64) {
        int np = bn * 64 + tid;
        sBias[tid] = g_bias[np >> 10][np & 1023];
    }

    const int v1 = tid + 256;
    const int b0s = tid >> 4, kq0 = (tid & 15) * 4;
    const int b1s = v1 >> 4,  kq1 = (v1 & 15) * 4;
    const int brow0 = (mh * 16 + (lane >> 2)) * 68 + (lane & 3);
    const int brow1 = (mh * 16 + 8 + (lane >> 2)) * 68 + (lane & 3);

    const float* tilebase = sA + ta * 8192;
    const int gate = (bn * 64) >> 10;
    const int nbase = (bn * 64) & 1023;
    __syncthreads();

    for (int mc = 0; mc < 256; mc++) {
        const int m0 = bm * 8192 + mc * 32;

        float acc[2][4];
#pragma unroll
        for (int g = 0; g < 2; g++)
#pragma unroll
            for (int j = 0; j < 4; j++) acc[g][j] = 0.f;

        float4 px0 = __ldg((const float4*)(X + (size_t)(m0 + b0s) * II + kq0));
        float4 px1 = __ldg((const float4*)(X + (size_t)(m0 + b1s) * II + kq1));

        for (int j = 0; j < 8; j++) {
            float* xb = sX + (j & 1) * 2176;
            __syncthreads();
            st4tf(xb + b0s * 68 + kq0, px0);
            st4tf(xb + b1s * 68 + kq1, px1);
            __syncthreads();
            if (j < 7) {
                int k1 = (j + 1) * 64;
                px0 = __ldg((const float4*)(X + (size_t)(m0 + b0s) * II + k1 + kq0));
                px1 = __ldg((const float4*)(X + (size_t)(m0 + b1s) * II + k1 + kq1));
            }
#pragma unroll
            for (int kt = 0; kt < 8; kt++) {
                const int colo = kt * 8;
                unsigned x0a = *(const unsigned*)(xb + brow0 + colo);
                unsigned x1a = *(const unsigned*)(xb + brow0 + colo + 4);
                unsigned x0b = *(const unsigned*)(xb + brow1 + colo);
                unsigned x1b = *(const unsigned*)(xb + brow1 + colo + 4);
                uint4 a = *(const uint4*)(tilebase + (j * 8 + kt) * 128 + lane * 4);
                mma_tf32(acc[0], a, x0a, x1a);
                mma_tf32(acc[1], a, x0b, x1b);
            }
        }

        __syncthreads();
#pragma unroll
        for (int g = 0; g < 2; g++)
#pragma unroll
            for (int j = 0; j < 4; j++) {
                int nrow = ta * 16 + (lane >> 2) + 8 * (j >> 1);
                int mcol = mh * 16 + g * 8 + 2 * (lane & 3) + (j & 1);
                sT[mcol * 68 + nrow] = acc[g][j];
            }
        __syncthreads();
#pragma unroll
        for (int e = 0; e < 2; e++) {
            int idx = tid + e * 256;
            int row = idx >> 4, q = idx & 15;
            float4 v = *(float4*)(sT + row * 68 + q * 4);
            v.x += sBias[q * 4 + 0]; v.y += sBias[q * 4 + 1];
            v.z += sBias[q * 4 + 2]; v.w += sBias[q * 4 + 3];
            *(float4*)(g_P + (size_t)gate * TBH + (size_t)(m0 + row) * HH + nbase + q * 4) = v;
        }
    }
}

// persistent tf32 recurrence: block owns 8 n-cols across all 6 matrices.
#define SMEM_FLOATS (49152 + 8704)
extern "C" __global__ void __launch_bounds__(256) lstm_kernel(float* __restrict__ out)
{
    extern __shared__ float smem[];
    float* sW  = smem;              // 3 tiles x 16384
    float* sB  = smem + 49152;      // staging + reduction (8704)
    float* sBh = sB;                // 2 x 2176
    float* sBc = sB + 2 * 2176;     // 2 x 2176

    const int tid = threadIdx.x, bId = blockIdx.x;
    const int w = tid >> 5, lane = tid & 31;
    const int kw = w >> 1, bgset = w & 1;

    const int s0 = 3 * bId;
#pragma unroll
    for (int tt = 0; tt < 3; tt++) {
        const float4* src = (const float4*)(g_Wpk + (size_t)(s0 + tt) * 16384);
        float4* dst = (float4*)(sW + tt * 16384);
        for (int p = tid; p < 4096; p += 256) dst[p] = __ldg(src + p);
    }

    const int v1 = tid + 256;
    const int b0s = tid >> 4, kq0 = (tid & 15) * 4;
    const int b1s = v1 >> 4,  kq1 = (v1 & 15) * 4;
    const int brow0 = (bgset * 16 + (lane >> 2)) * 68 + (lane & 3);
    const int brow1 = (bgset * 16 + 8 + (lane >> 2)) * 68 + (lane & 3);

    // pointwise ownership (warps 0,1 only): col nl, 4 (g,jb) batch slots
    const int nl = lane >> 2;
    const int nown = bId * 8 + nl;
    int offs[4];
#pragma unroll
    for (int gj = 0; gj < 4; gj++) {
        int g = gj >> 1, jb = gj & 1;
        int bcol = bgset * 16 + g * 8 + 2 * (lane & 3) + jb;
        offs[gj] = bcol * HH + nown;
    }

    __syncthreads();

    for (int t = 0; t < TT; t++) {
        const int cur = t & 1, nxt = cur ^ 1;
        const float* c_in = g_c[cur];

        // prefetch pointwise operands (warps 0,1)
        float pP[4][4], pC[4];
        if (w < 2) {
#pragma unroll
            for (int gj = 0; gj < 4; gj++) {
                size_t pb = (size_t)t * BH + offs[gj];
                pP[0][gj] = __ldg(&g_P[pb]);
                pP[1][gj] = __ldg(&g_P[(size_t)TBH + pb]);
                pP[2][gj] = __ldg(&g_P[2 * (size_t)TBH + pb]);
                pP[3][gj] = __ldg(&g_P[3 * (size_t)TBH + pb]);
                pC[gj] = __ldcg(&c_in[offs[gj]]);
            }
        }

        // ---------- phase 1: tiles 0,1 (x h), tile 2 (x c) ----------
        float acc[3][2][4];
#pragma unroll
        for (int a = 0; a < 3; a++)
#pragma unroll
            for (int g = 0; g < 2; g++)
#pragma unroll
                for (int j = 0; j < 4; j++) acc[a][g][j] = 0.f;

        float4 ph0 = __ldcg((const float4*)(g_h + b0s * HH + kq0));
        float4 ph1 = __ldcg((const float4*)(g_h + b1s * HH + kq1));
        float4 pc0 = __ldcg((const float4*)(c_in + b0s * HH + kq0));
        float4 pc1 = __ldcg((const float4*)(c_in + b1s * HH + kq1));

        for (int j = 0; j < 16; j++) {
            float* bh = sBh + (j & 1) * 2176;
            float* bc = sBc + (j & 1) * 2176;
            __syncthreads();
            st4tf(bh + b0s * 68 + kq0, ph0); st4tf(bh + b1s * 68 + kq1, ph1);
            st4tf(bc + b0s * 68 + kq0, pc0); st4tf(bc + b1s * 68 + kq1, pc1);
            __syncthreads();
            if (j < 15) {
                int k1 = (j + 1) * 64;
                ph0 = __ldcg((const float4*)(g_h + b0s * HH + k1 + kq0));
                ph1 = __ldcg((const float4*)(g_h + b1s * HH + k1 + kq1));
                pc0 = __ldcg((const float4*)(c_in + b0s * HH + k1 + kq0));
                pc1 = __ldcg((const float4*)(c_in + b1s * HH + k1 + kq1));
            }
#pragma unroll
            for (int q = 0; q < 2; q++) {
                const int kt = kw * 2 + q, colo = kt * 8;
                unsigned h0a = *(const unsigned*)(bh + brow0 + colo);
                unsigned h1a = *(const unsigned*)(bh + brow0 + colo + 4);
                unsigned h0b = *(const unsigned*)(bh + brow1 + colo);
                unsigned h1b = *(const unsigned*)(bh + brow1 + colo + 4);
                unsigned c0a = *(const unsigned*)(bc + brow0 + colo);
                unsigned c1a = *(const unsigned*)(bc + brow0 + colo + 4);
                unsigned c0b = *(const unsigned*)(bc + brow1 + colo);
                unsigned c1b = *(const unsigned*)(bc + brow1 + colo + 4);
                const int gkt = j * 8 + kt;
                uint4 a0 = *(const uint4*)(sW + gkt * 128 + lane * 4);
                uint4 a1 = *(const uint4*)(sW + 16384 + gkt * 128 + lane * 4);
                uint4 a2 = *(const uint4*)(sW + 32768 + gkt * 128 + lane * 4);
                mma_tf32(acc[0][0], a0, h0a, h1a);
                mma_tf32(acc[0][1], a0, h0b, h1b);
                mma_tf32(acc[1][0], a1, h0a, h1a);
                mma_tf32(acc[1][1], a1, h0b, h1b);
                mma_tf32(acc[2][0], a2, c0a, c1a);
                mma_tf32(acc[2][1], a2, c0b, c1b);
            }
        }

        // cross-k-split reduction in smem; kw==0 (warps 0,1) hold totals
        __syncthreads();
        if (kw > 0) {
            float* dst = sB + (((kw - 1) * 2 + bgset) * 32 + lane) * 24;
#pragma unroll
            for (int a = 0; a < 3; a++)
#pragma unroll
                for (int g = 0; g < 2; g++)
#pragma unroll
                    for (int j = 0; j < 4; j++) dst[a * 8 + g * 4 + j] = acc[a][g][j];
        }
        __syncthreads();
        if (kw == 0) {
#pragma unroll
            for (int r = 0; r < 3; r++) {
                const float* sp = sB + ((r * 2 + bgset) * 32 + lane) * 24;
#pragma unroll
                for (int a = 0; a < 3; a++)
#pragma unroll
                    for (int g = 0; g < 2; g++)
#pragma unroll
                        for (int j = 0; j < 4; j++) acc[a][g][j] += sp[a * 8 + g * 4 + j];
            }
            // ---------- local pointwise: gates, cy, po ----------
#pragma unroll
            for (int gj = 0; gj < 4; gj++) {
                int g = gj >> 1, jb = gj & 1;
                float hi = acc[0][g][jb],     hf = acc[0][g][2 + jb];
                float hc = acc[1][g][jb],     ho = acc[1][g][2 + jb];
                float ci = acc[2][g][jb],     cf = acc[2][g][2 + jb];
                float pi = pP[0][gj] + hi + ci;
                float pf = pP[1][gj] + hf + cf;
                float pg = pP[2][gj] + hc;
                float po = pP[3][gj] + ho;
                float iv = 1.f / (1.f + expf(-pi));
                float fv = 1.f / (1.f + expf(-pf));
                float gv = tanhf(pg);
                float cy = fmaf(fv, pC[gj], iv * gv);
                g_c[nxt][offs[gj]] = cy;
                g_po[offs[gj]] = po;
            }
        }
        // barrier B: all arrive (cy published); only phase-2 blocks wait
        gbar(&g_cntB, &g_genB, 128, (unsigned)(t + 1), true, bId < 64);

        // ---------- phase 2 (blocks 0..63): o = sig(po + cy@Wcyo^T) ----------
        if (bId < 64) {
            float acc2[2][4];
#pragma unroll
            for (int g = 0; g < 2; g++)
#pragma unroll
                for (int j = 0; j < 4; j++) acc2[g][j] = 0.f;

            float* sCy = sBh;
            float* sA2 = sBc;
            const float* cyp = g_c[nxt];
            const float* wsrc = g_Wpk + (size_t)(384 + bId) * 16384;

            float4 py0 = __ldcg((const float4*)(cyp + b0s * HH + kq0));
            float4 py1 = __ldcg((const float4*)(cyp + b1s * HH + kq1));
            float4 pa  = __ldg((const float4*)(wsrc) + tid);

            for (int j = 0; j < 16; j++) {
                float* cb = sCy + (j & 1) * 2176;
                float* ab = sA2 + (j & 1) * 1088;
                __syncthreads();
                st4tf(cb + b0s * 68 + kq0, py0);
                st4tf(cb + b1s * 68 + kq1, py1);
                *(float4*)(ab + tid * 4) = pa;
                __syncthreads();
                if (j < 15) {
                    int k1 = (j + 1) * 64;
                    py0 = __ldcg((const float4*)(cyp + b0s * HH + k1 + kq0));
                    py1 = __ldcg((const float4*)(cyp + b1s * HH + k1 + kq1));
                    pa  = __ldg((const float4*)(wsrc + (j + 1) * 1024) + tid);
                }
#pragma unroll
                for (int q = 0; q < 2; q++) {
                    const int kt = kw * 2 + q, colo = kt * 8;
                    unsigned y0a = *(const unsigned*)(cb + brow0 + colo);
                    unsigned y1a = *(const unsigned*)(cb + brow0 + colo + 4);
                    unsigned y0b = *(const unsigned*)(cb + brow1 + colo);
                    unsigned y1b = *(const unsigned*)(cb + brow1 + colo + 4);
                    uint4 af = *(const uint4*)(ab + kt * 128 + lane * 4);
                    mma_tf32(acc2[0], af, y0a, y1a);
                    mma_tf32(acc2[1], af, y0b, y1b);
                }
            }

            __syncthreads();
            if (kw > 0) {
                float* dst = sCy + (((kw - 1) * 2 + bgset) * 32 + lane) * 8;
#pragma unroll
                for (int g = 0; g < 2; g++)
#pragma unroll
                    for (int j = 0; j < 4; j++) dst[g * 4 + j] = acc2[g][j];
            }
            __syncthreads();
            if (kw == 0) {
#pragma unroll
                for (int r = 0; r < 3; r++) {
                    const float* sp = sCy + ((r * 2 + bgset) * 32 + lane) * 8;
#pragma unroll
                    for (int g = 0; g < 2; g++)
#pragma unroll
                        for (int j = 0; j < 4; j++) acc2[g][j] += sp[g * 4 + j];
                }
#pragma unroll
                for (int g = 0; g < 2; g++)
#pragma unroll
                    for (int j = 0; j < 4; j++) {
                        int row = bId * 16 + (lane >> 2) + 8 * (j >> 1);
                        int bcol = bgset * 16 + g * 8 + 2 * (lane & 3) + (j & 1);
                        int off = bcol * HH + row;
                        float po = __ldcg(&g_po[off]);
                        float cyv = __ldcg(&g_c[nxt][off]);
                        float o = 1.f / (1.f + expf(-(po + acc2[g][j])));
                        float hy = o * tanhf(cyv);
                        g_h[off] = hy;
                        out[(size_t)t * BH + off] = hy;
                    }
            }
        }
        // barrier C: phase-2 blocks arrive (h published); everyone waits
        gbar(&g_cntC, &g_genC, 64, (unsigned)(t + 1), bId < 64, true);
    }
}

extern "C" void kernel_launch(void* const* d_in, const int* in_sizes, int n_in,
                              void* d_out, int out_size)
{
    const float* X     = (const float*)d_in[0];
    const float* h0    = (const float*)d_in[1];
    const float* c0    = (const float*)d_in[2];
    const float* w_ii  = (const float*)d_in[3];
    const float* w_hi  = (const float*)d_in[4];
    const float* w_ci  = (const float*)d_in[5];
    const float* w_if  = (const float*)d_in[6];
    const float* w_hf  = (const float*)d_in[7];
    const float* w_cf  = (const float*)d_in[8];
    const float* w_ic  = (const float*)d_in[9];
    const float* w_hc  = (const float*)d_in[10];
    const float* w_io  = (const float*)d_in[11];
    const float* w_ho  = (const float*)d_in[12];
    const float* w_cyo = (const float*)d_in[13];
    float* out = (float*)d_out;

    cudaFuncSetAttribute(lstm_kernel,
                         cudaFuncAttributeMaxDynamicSharedMemorySize,
                         SMEM_FLOATS * 4);
    cudaFuncSetAttribute(proj2_kernel,
                         cudaFuncAttributeMaxDynamicSharedMemorySize,
                         PROJ_SMEM * 4);

    init_kernel<<<128, 256>>>(h0, c0,
        (const float*)d_in[14], (const float*)d_in[15], (const float*)d_in[16],
        (const float*)d_in[17], (const float*)d_in[18], (const float*)d_in[19],
        (const float*)d_in[20], (const float*)d_in[21], (const float*)d_in[22],
        (const float*)d_in[23], (const float*)d_in[24]);
    pack_kernel<<<28672, 256>>>(w_hi, w_hf, w_hc, w_ho, w_ci, w_cf, w_cyo);
    pack_in_kernel<<<8192, 256>>>(w_ii, w_if, w_ic, w_io);
    proj2_kernel<<<128, 256, PROJ_SMEM * 4>>>(X);
    lstm_kernel<<<NBLK, 256, SMEM_FLOATS * 4>>>(out);
}

// round 8
// speedup vs baseline: 1.8433x; 1.2702x over previous
#include <cuda_runtime.h>
#include <math.h>

#define TT 512
#define BB 32
#define II 512
#define HH 1024
#define BH (BB*HH)
#define TBH (TT*BB*HH)
#define NBLK 128

__device__ float g_P[(size_t)4 * TBH];
__device__ float g_h[BH];
__device__ float g_c[2][BH];
__device__ float g_po[BH];
__device__ float g_bias[4][HH];
__device__ float g_Wpk[(size_t)448 * 16384];      // 384 phase1 tiles + 64 Wcyo tiles
__device__ float g_WpkI[(size_t)4 * 64 * 8192];   // input weights, frag-packed
__device__ __align__(16) unsigned g_fB[128];
__device__ __align__(16) unsigned g_fC[128];
__device__ volatile unsigned g_genB;
__device__ volatile unsigned g_genC;

__device__ __forceinline__ unsigned cvt_tf32(float x) {
    unsigned r; asm("cvt.rna.tf32.f32 %0, %1;" : "=r"(r) : "f"(x)); return r;
}
__device__ __forceinline__ void st4tf(float* p, float4 v) {
    uint4 u; u.x = cvt_tf32(v.x); u.y = cvt_tf32(v.y);
    u.z = cvt_tf32(v.z); u.w = cvt_tf32(v.w); *(uint4*)p = u;
}
__device__ __forceinline__ void mma_tf32(float* d, uint4 a, unsigned b0, unsigned b1) {
    asm("mma.sync.aligned.m16n8k8.row.col.f32.tf32.tf32.f32 "
        "{%0,%1,%2,%3},{%4,%5,%6,%7},{%8,%9},{%0,%1,%2,%3};"
        : "+f"(d[0]), "+f"(d[1]), "+f"(d[2]), "+f"(d[3])
        : "r"(a.x), "r"(a.y), "r"(a.z), "r"(a.w), "r"(b0), "r"(b1));
}

// arrive: per-block flag store (distinct addresses, no atomic contention)
__device__ __forceinline__ void bar_arrive(unsigned* f, int bId, unsigned v) {
    __syncthreads();
    if (threadIdx.x == 0) {
        __threadfence();
        asm volatile("st.relaxed.gpu.global.u32 [%0], %1;"
                     :: "l"(f + bId), "r"(v) : "memory");
    }
}
// master (block 0): one warp polls all flags, then publishes generation
__device__ __forceinline__ void bar_master(const unsigned* f, int n, unsigned v,
                                           volatile unsigned* gen) {
    if (threadIdx.x < 32) {
        int i = threadIdx.x * 4;
        bool act = i < n;
        const unsigned* p = f + i;
        for (;;) {
            unsigned x0 = v, x1 = v, x2 = v, x3 = v;
            if (act)
                asm volatile("ld.relaxed.gpu.global.v4.u32 {%0,%1,%2,%3},[%4];"
                             : "=r"(x0), "=r"(x1), "=r"(x2), "=r"(x3) : "l"(p));
            bool ok = (x0 >= v) && (x1 >= v) && (x2 >= v) && (x3 >= v);
            if (__all_sync(0xffffffffu, ok)) break;
        }
        __threadfence();
        if (threadIdx.x == 0) *gen = v;
    }
    __syncthreads();
}
// non-master: one thread spins on the generation word
__device__ __forceinline__ void bar_spin(volatile unsigned* gen, unsigned v) {
    if (threadIdx.x == 0) {
        while (*gen < v) { }
        __threadfence();
    }
    __syncthreads();
}

__global__ void __launch_bounds__(256) init_kernel(
    const float* __restrict__ h0, const float* __restrict__ c0,
    const float* __restrict__ b_ii, const float* __restrict__ b_hi,
    const float* __restrict__ b_ci, const float* __restrict__ b_if,
    const float* __restrict__ b_hf, const float* __restrict__ b_cf,
    const float* __restrict__ b_ic, const float* __restrict__ b_hc,
    const float* __restrict__ b_io, const float* __restrict__ b_ho,
    const float* __restrict__ b_cyo)
{
    int i = blockIdx.x * blockDim.x + threadIdx.x;
    if (i < BH) { g_h[i] = h0[i]; g_c[0][i] = c0[i]; }
    if (i < HH) {
        g_bias[0][i] = b_ii[i] + b_hi[i] + b_ci[i];
        g_bias[1][i] = b_if[i] + b_hf[i] + b_cf[i];
        g_bias[2][i] = b_ic[i] + b_hc[i];
        g_bias[3][i] = b_io[i] + b_ho[i] + b_cyo[i];
    }
    if (i < 128) { g_fB[i] = 0; g_fC[i] = 0; }
    if (i == 0) { g_genB = 0; g_genC = 0; }
}

// Pack weights into m16n8k8 A-fragment order.
// Tiles 0..383: phase-1; tile s = 3*bId + tt; A-row r -> mat = tt*2 + (r>>3),
// n = bId*8 + (r&7). Tiles 384..447: Wcyo, row = ng*16 + r.
__global__ void __launch_bounds__(256) pack_kernel(
    const float* __restrict__ w0, const float* __restrict__ w1,
    const float* __restrict__ w2, const float* __restrict__ w3,
    const float* __restrict__ w4, const float* __restrict__ w5,
    const float* __restrict__ w6)
{
    int gid = blockIdx.x * 256 + threadIdx.x;
    int s = gid >> 14, rem = gid & 16383;
    int kt = rem >> 7, lane = (rem >> 2) & 31, jj = rem & 3;
    int kcol = kt * 8 + (lane & 3) + 4 * (jj >> 1);
    float v;
    if (s < 384) {
        int bId = s / 3, tt = s - 3 * bId;
        int r = (lane >> 2) + 8 * (jj & 1);
        int mat = tt * 2 + (r >> 3);
        int n = bId * 8 + (r & 7);
        const float* W = (mat == 0) ? w0 : (mat == 1) ? w1 : (mat == 2) ? w2 :
                         (mat == 3) ? w3 : (mat == 4) ? w4 : w5;
        v = __ldg(&W[n * HH + kcol]);
    } else {
        int ng = s - 384;
        int row = ng * 16 + (lane >> 2) + 8 * (jj & 1);
        v = __ldg(&w6[row * HH + kcol]);
    }
    g_Wpk[gid] = __uint_as_float(cvt_tf32(v));
}

__global__ void __launch_bounds__(256) pack_in_kernel(
    const float* __restrict__ w0, const float* __restrict__ w1,
    const float* __restrict__ w2, const float* __restrict__ w3)
{
    int gid = blockIdx.x * 256 + threadIdx.x;
    int mat = gid >> 19, rem = gid & 524287;
    int ng = rem >> 13, kt = (rem >> 7) & 63, lane = (rem >> 2) & 31, jj = rem & 3;
    int row = ng * 16 + (lane >> 2) + 8 * (jj & 1);
    int col = kt * 8 + (lane & 3) + 4 * (jj >> 1);
    const float* W = (mat == 0) ? w0 : (mat == 1) ? w1 : (mat == 2) ? w2 : w3;
    g_WpkI[gid] = __uint_as_float(cvt_tf32(__ldg(&W[row * II + col])));
}

// proj (tf32 mma): P[g][m][n] = X @ Wg^T + bias
#define PROJ_SMEM (32768 + 2*2176 + 2176 + 64)
__global__ void __launch_bounds__(256) proj2_kernel(const float* __restrict__ X)
{
    extern __shared__ float smem[];
    float* sA = smem;
    float* sX = smem + 32768;
    float* sT = smem + 32768 + 4352;
    float* sBias = sT + 2176;

    const int tid = threadIdx.x;
    const int bn = blockIdx.x & 63, bm = blockIdx.x >> 6;
    const int w = tid >> 5, lane = tid & 31;
    const int ta = w >> 1, mh = w & 1;

    {
        const float4* src = (const float4*)(g_WpkI + (size_t)(bn * 4) * 8192);
        float4* dst = (float4*)sA;
        for (int p = tid; p < 8192; p += 256) dst[p] = __ldg(src + p);
    }
    if (tid < 64) {
        int np = bn * 64 + tid;
        sBias[tid] = g_bias[np >> 10][np & 1023];
    }

    const int v1 = tid + 256;
    const int b0s = tid >> 4, kq0 = (tid & 15) * 4;
    const int b1s = v1 >> 4,  kq1 = (v1 & 15) * 4;
    const int brow0 = (mh * 16 + (lane >> 2)) * 68 + (lane & 3);
    const int brow1 = (mh * 16 + 8 + (lane >> 2)) * 68 + (lane & 3);

    const float* tilebase = sA + ta * 8192;
    const int gate = (bn * 64) >> 10;
    const int nbase = (bn * 64) & 1023;
    __syncthreads();

    for (int mc = 0; mc < 256; mc++) {
        const int m0 = bm * 8192 + mc * 32;

        float acc[2][4];
#pragma unroll
        for (int g = 0; g < 2; g++)
#pragma unroll
            for (int j = 0; j < 4; j++) acc[g][j] = 0.f;

        float4 px0 = __ldg((const float4*)(X + (size_t)(m0 + b0s) * II + kq0));
        float4 px1 = __ldg((const float4*)(X + (size_t)(m0 + b1s) * II + kq1));

        for (int j = 0; j < 8; j++) {
            float* xb = sX + (j & 1) * 2176;
            __syncthreads();
            st4tf(xb + b0s * 68 + kq0, px0);
            st4tf(xb + b1s * 68 + kq1, px1);
            __syncthreads();
            if (j < 7) {
                int k1 = (j + 1) * 64;
                px0 = __ldg((const float4*)(X + (size_t)(m0 + b0s) * II + k1 + kq0));
                px1 = __ldg((const float4*)(X + (size_t)(m0 + b1s) * II + k1 + kq1));
            }
#pragma unroll
            for (int kt = 0; kt < 8; kt++) {
                const int colo = kt * 8;
                unsigned x0a = *(const unsigned*)(xb + brow0 + colo);
                unsigned x1a = *(const unsigned*)(xb + brow0 + colo + 4);
                unsigned x0b = *(const unsigned*)(xb + brow1 + colo);
                unsigned x1b = *(const unsigned*)(xb + brow1 + colo + 4);
                uint4 a = *(const uint4*)(tilebase + (j * 8 + kt) * 128 + lane * 4);
                mma_tf32(acc[0], a, x0a, x1a);
                mma_tf32(acc[1], a, x0b, x1b);
            }
        }

        __syncthreads();
#pragma unroll
        for (int g = 0; g < 2; g++)
#pragma unroll
            for (int j = 0; j < 4; j++) {
                int nrow = ta * 16 + (lane >> 2) + 8 * (j >> 1);
                int mcol = mh * 16 + g * 8 + 2 * (lane & 3) + (j & 1);
                sT[mcol * 68 + nrow] = acc[g][j];
            }
        __syncthreads();
#pragma unroll
        for (int e = 0; e < 2; e++) {
            int idx = tid + e * 256;
            int row = idx >> 4, q = idx & 15;
            float4 v = *(float4*)(sT + row * 68 + q * 4);
            v.x += sBias[q * 4 + 0]; v.y += sBias[q * 4 + 1];
            v.z += sBias[q * 4 + 2]; v.w += sBias[q * 4 + 3];
            *(float4*)(g_P + (size_t)gate * TBH + (size_t)(m0 + row) * HH + nbase + q * 4) = v;
        }
    }
}

// persistent tf32 recurrence
#define SMEM_FLOATS (49152 + 8704)
extern "C" __global__ void __launch_bounds__(256) lstm_kernel(float* __restrict__ out)
{
    extern __shared__ float smem[];
    float* sW  = smem;              // 3 tiles x 16384
    float* sB  = smem + 49152;      // staging + reduction (8704)
    float* sBh = sB;                // phase1: 2 x 2176 (h)
    float* sBc = sB + 2 * 2176;     // phase1: 2 x 2176 (c)

    const int tid = threadIdx.x, bId = blockIdx.x;
    const int w = tid >> 5, lane = tid & 31;
    const int kw = w >> 1, bgset = w & 1;

    const int s0 = 3 * bId;
#pragma unroll
    for (int tt = 0; tt < 3; tt++) {
        const float4* src = (const float4*)(g_Wpk + (size_t)(s0 + tt) * 16384);
        float4* dst = (float4*)(sW + tt * 16384);
        for (int p = tid; p < 4096; p += 256) dst[p] = __ldg(src + p);
    }

    const int v1 = tid + 256;
    const int b0s = tid >> 4, kq0 = (tid & 15) * 4;
    const int b1s = v1 >> 4,  kq1 = (v1 & 15) * 4;
    const int brow0 = (bgset * 16 + (lane >> 2)) * 68 + (lane & 3);
    const int brow1 = (bgset * 16 + 8 + (lane >> 2)) * 68 + (lane & 3);

    // pointwise ownership (warps 0,1): col nl, 4 (g,jb) batch slots
    const int nl = lane >> 2;
    const int nown = bId * 8 + nl;
    int offs[4];
#pragma unroll
    for (int gj = 0; gj < 4; gj++) {
        int g = gj >> 1, jb = gj & 1;
        int bcol = bgset * 16 + g * 8 + 2 * (lane & 3) + jb;
        offs[gj] = bcol * HH + nown;
    }

    // phase2 block roles: tile ng, batch half
    const int half = bId >> 6, ng = bId & 63;
    const float* wsrc2 = g_Wpk + (size_t)(384 + ng) * 16384;
    const int crow = tid >> 4, cq = (tid & 15) * 4;     // cy staging role
    const int prow0 = (lane >> 2) * 68 + (lane & 3);
    const int prow1 = prow0 + 8 * 68;
    float* sCy = sB;                 // 2 x 1088
    float* sA2 = sB + 2176;          // 2 x 1088
    float* sRed = sB + 4352;         // 7*32*8 = 1792

    __syncthreads();

    for (int t = 0; t < TT; t++) {
        const int cur = t & 1, nxt = cur ^ 1;
        const float* c_in = g_c[cur];

        // prefetch pointwise operands (warps 0,1)
        float pP[4][4], pC[4];
        if (w < 2) {
#pragma unroll
            for (int gj = 0; gj < 4; gj++) {
                size_t pb = (size_t)t * BH + offs[gj];
                pP[0][gj] = __ldg(&g_P[pb]);
                pP[1][gj] = __ldg(&g_P[(size_t)TBH + pb]);
                pP[2][gj] = __ldg(&g_P[2 * (size_t)TBH + pb]);
                pP[3][gj] = __ldg(&g_P[3 * (size_t)TBH + pb]);
                pC[gj] = __ldcg(&c_in[offs[gj]]);
            }
        }

        // ---------- phase 1: tiles 0,1 (x h), tile 2 (x c) ----------
        float acc[3][2][4];
#pragma unroll
        for (int a = 0; a < 3; a++)
#pragma unroll
            for (int g = 0; g < 2; g++)
#pragma unroll
                for (int j = 0; j < 4; j++) acc[a][g][j] = 0.f;

        // prologue: stage chunk 0, prefetch chunk 1
        float4 rh0 = __ldcg((const float4*)(g_h  + b0s * HH + kq0));
        float4 rh1 = __ldcg((const float4*)(g_h  + b1s * HH + kq1));
        float4 rc0 = __ldcg((const float4*)(c_in + b0s * HH + kq0));
        float4 rc1 = __ldcg((const float4*)(c_in + b1s * HH + kq1));
        st4tf(sBh + b0s * 68 + kq0, rh0); st4tf(sBh + b1s * 68 + kq1, rh1);
        st4tf(sBc + b0s * 68 + kq0, rc0); st4tf(sBc + b1s * 68 + kq1, rc1);
        rh0 = __ldcg((const float4*)(g_h  + b0s * HH + 64 + kq0));
        rh1 = __ldcg((const float4*)(g_h  + b1s * HH + 64 + kq1));
        rc0 = __ldcg((const float4*)(c_in + b0s * HH + 64 + kq0));
        rc1 = __ldcg((const float4*)(c_in + b1s * HH + 64 + kq1));
        __syncthreads();

        for (int j = 0; j < 16; j++) {
            float* bh = sBh + (j & 1) * 2176;
            float* bc = sBc + (j & 1) * 2176;
            if (j < 15) {
                float* bhn = sBh + ((j + 1) & 1) * 2176;
                float* bcn = sBc + ((j + 1) & 1) * 2176;
                st4tf(bhn + b0s * 68 + kq0, rh0); st4tf(bhn + b1s * 68 + kq1, rh1);
                st4tf(bcn + b0s * 68 + kq0, rc0); st4tf(bcn + b1s * 68 + kq1, rc1);
                if (j < 14) {
                    int k2 = (j + 2) * 64;
                    rh0 = __ldcg((const float4*)(g_h  + b0s * HH + k2 + kq0));
                    rh1 = __ldcg((const float4*)(g_h  + b1s * HH + k2 + kq1));
                    rc0 = __ldcg((const float4*)(c_in + b0s * HH + k2 + kq0));
                    rc1 = __ldcg((const float4*)(c_in + b1s * HH + k2 + kq1));
                }
            }
#pragma unroll
            for (int q = 0; q < 2; q++) {
                const int kt = kw * 2 + q, colo = kt * 8;
                unsigned h0a = *(const unsigned*)(bh + brow0 + colo);
                unsigned h1a = *(const unsigned*)(bh + brow0 + colo + 4);
                unsigned h0b = *(const unsigned*)(bh + brow1 + colo);
                unsigned h1b = *(const unsigned*)(bh + brow1 + colo + 4);
                unsigned c0a = *(const unsigned*)(bc + brow0 + colo);
                unsigned c1a = *(const unsigned*)(bc + brow0 + colo + 4);
                unsigned c0b = *(const unsigned*)(bc + brow1 + colo);
                unsigned c1b = *(const unsigned*)(bc + brow1 + colo + 4);
                const int gkt = j * 8 + kt;
                uint4 a0 = *(const uint4*)(sW + gkt * 128 + lane * 4);
                uint4 a1 = *(const uint4*)(sW + 16384 + gkt * 128 + lane * 4);
                uint4 a2 = *(const uint4*)(sW + 32768 + gkt * 128 + lane * 4);
                mma_tf32(acc[0][0], a0, h0a, h1a);
                mma_tf32(acc[0][1], a0, h0b, h1b);
                mma_tf32(acc[1][0], a1, h0a, h1a);
                mma_tf32(acc[1][1], a1, h0b, h1b);
                mma_tf32(acc[2][0], a2, c0a, c1a);
                mma_tf32(acc[2][1], a2, c0b, c1b);
            }
            __syncthreads();
        }

        // cross-k-split reduction; warps 0,1 (kw==0) hold totals
        if (kw > 0) {
            float* dst = sB + (((kw - 1) * 2 + bgset) * 32 + lane) * 24;
#pragma unroll
            for (int a = 0; a < 3; a++)
#pragma unroll
                for (int g = 0; g < 2; g++)
#pragma unroll
                    for (int j = 0; j < 4; j++) dst[a * 8 + g * 4 + j] = acc[a][g][j];
        }
        __syncthreads();
        if (kw == 0) {
#pragma unroll
            for (int r = 0; r < 3; r++) {
                const float* sp = sB + ((r * 2 + bgset) * 32 + lane) * 24;
#pragma unroll
                for (int a = 0; a < 3; a++)
#pragma unroll
                    for (int g = 0; g < 2; g++)
#pragma unroll
                        for (int j = 0; j < 4; j++) acc[a][g][j] += sp[a * 8 + g * 4 + j];
            }
            // local pointwise: gates, cy, po
#pragma unroll
            for (int gj = 0; gj < 4; gj++) {
                int g = gj >> 1, jb = gj & 1;
                float hi = acc[0][g][jb],     hf = acc[0][g][2 + jb];
                float hc = acc[1][g][jb],     ho = acc[1][g][2 + jb];
                float ci = acc[2][g][jb],     cf = acc[2][g][2 + jb];
                float pi = pP[0][gj] + hi + ci;
                float pf = pP[1][gj] + hf + cf;
                float pg = pP[2][gj] + hc;
                float po = pP[3][gj] + ho;
                float iv = 1.f / (1.f + expf(-pi));
                float fv = 1.f / (1.f + expf(-pf));
                float gv = tanhf(pg);
                float cy = fmaf(fv, pC[gj], iv * gv);
                g_c[nxt][offs[gj]] = cy;
                g_po[offs[gj]] = po;
            }
        }
        // barrier B (cy/po published)
        bar_arrive(g_fB, bId, (unsigned)(t + 1));
        if (bId == 0) bar_master(g_fB, 128, (unsigned)(t + 1), &g_genB);
        else          bar_spin(&g_genB, (unsigned)(t + 1));

        // ---------- phase 2 (all 128 blocks): o = sig(po + cy@Wcyo^T) ------
        {
            const float* cyp = g_c[nxt];
            const float* cyb = cyp + half * 16 * HH;

            // epilogue operand prefetch (warp 0)
            float ppo[2][4], pcy[2][4];
            if (w == 0) {
#pragma unroll
                for (int g = 0; g < 2; g++)
#pragma unroll
                    for (int j = 0; j < 4; j++) {
                        int row = ng * 16 + (lane >> 2) + 8 * (j >> 1);
                        int bcol = half * 16 + g * 8 + 2 * (lane & 3) + (j & 1);
                        int off = bcol * HH + row;
                        ppo[g][j] = __ldcg(&g_po[off]);
                        pcy[g][j] = __ldcg(&cyp[off]);
                    }
            }

            float acc2[2][4];
#pragma unroll
            for (int g = 0; g < 2; g++)
#pragma unroll
                for (int j = 0; j < 4; j++) acc2[g][j] = 0.f;

            // prologue: stage chunk 0, prefetch chunk 1
            float4 ry = __ldcg((const float4*)(cyb + crow * HH + cq));
            float4 ra = __ldg((const float4*)wsrc2 + tid);
            st4tf(sCy + crow * 68 + cq, ry);
            *(float4*)(sA2 + tid * 4) = ra;
            ry = __ldcg((const float4*)(cyb + crow * HH + 64 + cq));
            ra = __ldg((const float4*)(wsrc2 + 1024) + tid);
            __syncthreads();

            for (int j = 0; j < 16; j++) {
                float* cb = sCy + (j & 1) * 1088;
                float* ab = sA2 + (j & 1) * 1088;
                if (j < 15) {
                    st4tf(sCy + ((j + 1) & 1) * 1088 + crow * 68 + cq, ry);
                    *(float4*)(sA2 + ((j + 1) & 1) * 1088 + tid * 4) = ra;
                    if (j < 14) {
                        int k2 = (j + 2) * 64;
                        ry = __ldcg((const float4*)(cyb + crow * HH + k2 + cq));
                        ra = __ldg((const float4*)(wsrc2 + (j + 2) * 1024) + tid);
                    }
                }
                const int colo = w * 8;
                unsigned y0a = *(const unsigned*)(cb + prow0 + colo);
                unsigned y1a = *(const unsigned*)(cb + prow0 + colo + 4);
                unsigned y0b = *(const unsigned*)(cb + prow1 + colo);
                unsigned y1b = *(const unsigned*)(cb + prow1 + colo + 4);
                uint4 af = *(const uint4*)(ab + w * 128 + lane * 4);
                mma_tf32(acc2[0], af, y0a, y1a);
                mma_tf32(acc2[1], af, y0b, y1b);
                __syncthreads();
            }

            // reduce over 8 k-split warps
            if (w > 0) {
                float* dst = sRed + ((w - 1) * 32 + lane) * 8;
#pragma unroll
                for (int g = 0; g < 2; g++)
#pragma unroll
                    for (int j = 0; j < 4; j++) dst[g * 4 + j] = acc2[g][j];
            }
            __syncthreads();
            if (w == 0) {
#pragma unroll
                for (int r = 0; r < 7; r++) {
                    const float* sp = sRed + (r * 32 + lane) * 8;
#pragma unroll
                    for (int g = 0; g < 2; g++)
#pragma unroll
                        for (int j = 0; j < 4; j++) acc2[g][j] += sp[g * 4 + j];
                }
#pragma unroll
                for (int g = 0; g < 2; g++)
#pragma unroll
                    for (int j = 0; j < 4; j++) {
                        int row = ng * 16 + (lane >> 2) + 8 * (j >> 1);
                        int bcol = half * 16 + g * 8 + 2 * (lane & 3) + (j & 1);
                        int off = bcol * HH + row;
                        float o = 1.f / (1.f + expf(-(ppo[g][j] + acc2[g][j])));
                        float hy = o * tanhf(pcy[g][j]);
                        g_h[off] = hy;
                        out[(size_t)t * BH + off] = hy;
                    }
            }
        }
        // barrier C (h published)
        bar_arrive(g_fC, bId, (unsigned)(t + 1));
        if (bId == 0) bar_master(g_fC, 128, (unsigned)(t + 1), &g_genC);
        else          bar_spin(&g_genC, (unsigned)(t + 1));
    }
}

extern "C" void kernel_launch(void* const* d_in, const int* in_sizes, int n_in,
                              void* d_out, int out_size)
{
    const float* X     = (const float*)d_in[0];
    const float* h0    = (const float*)d_in[1];
    const float* c0    = (const float*)d_in[2];
    const float* w_ii  = (const float*)d_in[3];
    const float* w_hi  = (const float*)d_in[4];
    const float* w_ci  = (const float*)d_in[5];
    const float* w_if  = (const float*)d_in[6];
    const float* w_hf  = (const float*)d_in[7];
    const float* w_cf  = (const float*)d_in[8];
    const float* w_ic  = (const float*)d_in[9];
    const float* w_hc  = (const float*)d_in[10];
    const float* w_io  = (const float*)d_in[11];
    const float* w_ho  = (const float*)d_in[12];
    const float* w_cyo = (const float*)d_in[13];
    float* out = (float*)d_out;

    cudaFuncSetAttribute(lstm_kernel,
                         cudaFuncAttributeMaxDynamicSharedMemorySize,
                         SMEM_FLOATS * 4);
    cudaFuncSetAttribute(proj2_kernel,
                         cudaFuncAttributeMaxDynamicSharedMemorySize,
                         PROJ_SMEM * 4);

    init_kernel<<<128, 256>>>(h0, c0,
        (const float*)d_in[14], (const float*)d_in[15], (const float*)d_in[16],
        (const float*)d_in[17], (const float*)d_in[18], (const float*)d_in[19],
        (const float*)d_in[20], (const float*)d_in[21], (const float*)d_in[22],
        (const float*)d_in[23], (const float*)d_in[24]);
    pack_kernel<<<28672, 256>>>(w_hi, w_hf, w_hc, w_ho, w_ci, w_cf, w_cyo);
    pack_in_kernel<<<8192, 256>>>(w_ii, w_if, w_ic, w_io);
    proj2_kernel<<<128, 256, PROJ_SMEM * 4>>>(X);
    lstm_kernel<<<NBLK, 256, SMEM_FLOATS * 4>>>(out);
}